// round 16
// baseline (speedup 1.0000x reference)
#include <cuda_runtime.h>
#include <cstddef>

// Problem constants
#define NL 4
#define NB 32
#define NS 512
#define ND 768
#define MAX_SPAN 4

#define ND4 (ND / 4)                         // 192 float4 per row
#define LSTRIDE4 ((size_t)NB * NS * ND / 4)  // layer stride in float4
#define NDC 6                                // 128-wide d slices
#define TCHUNK 64                            // t per warp-tile
#define GRID 128                             // 128 blocks x 12 warps = 1536 exact

struct Raw4 { float4 a, b, c, d; };

// ---- raw 4-layer loads for row s (address clamp only; rows >= NS are
//      never accumulated because nk <= NS-1-t) ----
__device__ __forceinline__ Raw4 ldrow(const float4* __restrict__ base, int s)
{
    const int sc = s < NS - 1 ? s : NS - 1;
    const float4* p = base + (size_t)sc * ND4;
    Raw4 q;
    q.a = p[0];
    q.b = p[LSTRIDE4];
    q.c = p[2 * LSTRIDE4];
    q.d = p[3 * LSTRIDE4];
    return q;
}

__device__ __forceinline__ float4 redrow(const Raw4& q)
{
    float4 r;
    r.x = ((q.a.x + q.b.x) + (q.c.x + q.d.x)) * 0.25f;
    r.y = ((q.a.y + q.b.y) + (q.c.y + q.d.y)) * 0.25f;
    r.z = ((q.a.z + q.b.z) + (q.c.z + q.d.z)) * 0.25f;
    r.w = ((q.a.w + q.b.w) + (q.c.w + q.d.w)) * 0.25f;
    return r;
}

// ---- pooled output for one t: sum of first nk of {A,B,C,D} ----
__device__ __forceinline__ void emit(float4* __restrict__ op, int nk,
                                     const float4& A, const float4& B,
                                     const float4& C, const float4& D)
{
    float4 acc = make_float4(0.f, 0.f, 0.f, 0.f);
    if (nk > 0) { acc.x += A.x; acc.y += A.y; acc.z += A.z; acc.w += A.w; }
    if (nk > 1) { acc.x += B.x; acc.y += B.y; acc.z += B.z; acc.w += B.w; }
    if (nk > 2) { acc.x += C.x; acc.y += C.y; acc.z += C.z; acc.w += C.w; }
    if (nk > 3) { acc.x += D.x; acc.y += D.y; acc.z += D.z; acc.w += D.w; }
    __stcs(op, acc);
}

__device__ __forceinline__ int nk_for(int t, int mask_len, int span)
{
    int nk = 0;
    if (t < mask_len - 2) {
        nk = span;
        const int lim = NS - 1 - t;
        if (nk > lim) nk = lim;
        if (nk > MAX_SPAN) nk = MAX_SPAN;
        if (nk < 0) nk = 0;
    }
    return nk;
}

// r = row - t0, valid 0..67 (m1 covers 0..63, m2 covers 64..67)
__device__ __forceinline__ bool needed(unsigned long long m1, unsigned int m2, int r)
{
    return r < 64 ? (bool)((m1 >> r) & 1ull) : (bool)((m2 >> (r - 64)) & 1u);
}

// load row only if some output accumulates it; otherwise leave q untouched
#define LDROW_IF(q, r, s)                                         \
    do { if (needed(m1, m2, (r))) (q) = ldrow(base, (s)); } while (0)

__global__ __launch_bounds__(384, 1)
void lmencoder_warp6(const float* __restrict__ hs,
                     const int*   __restrict__ spans,
                     const int*   __restrict__ masks,
                     float*       __restrict__ out)
{
    const int lane = threadIdx.x & 31;
    const int wid  = threadIdx.x >> 5;          // 0..11
    const int tile = blockIdx.x * 12 + wid;     // 128*12 = 1536 exact
    const int dc   = tile % NDC;                // 0..5
    const int pair = tile / NDC;                // b*8 + tc
    const int b    = pair >> 3;
    const int tc   = pair & 7;
    const int t0   = tc * TCHUNK;
    const bool asc = (tc & 1) == 0;             // alternate direction by parity
    const int wbase = asc ? t0 : t0 + 60;       // first group's t

    const float4* base = reinterpret_cast<const float4*>(hs)
                         + (size_t)b * NS * ND4 + dc * 32 + lane;
    float4* obase = reinterpret_cast<float4*>(out)
                    + (size_t)b * NS * ND4 + dc * 32 + lane;

    // ---- prologue: 28 window loads issued unconditionally (DRAM busy early) ----
    const Raw4 p1 = ldrow(base, wbase + 1);
    const Raw4 p2 = ldrow(base, wbase + 2);
    const Raw4 p3 = ldrow(base, wbase + 3);
    const Raw4 p4 = ldrow(base, wbase + 4);
    const Raw4 p5 = ldrow(base, wbase + 5);
    const Raw4 p6 = ldrow(base, wbase + 6);
    const Raw4 p7 = ldrow(base, wbase + 7);

    // ---- mask_len + per-lane nk, overlapped with prologue load latency ----
    const int4* mrow4 = reinterpret_cast<const int4*>(masks + b * NS);
    int msum = 0;
    #pragma unroll
    for (int k = 0; k < 4; k++) {
        const int4 m = mrow4[lane + 32 * k];
        msum += (m.x + m.y) + (m.z + m.w);
    }
    #pragma unroll
    for (int off = 16; off; off >>= 1)
        msum += __shfl_xor_sync(0xffffffffu, msum, off);
    const int mask_len = msum;

    const int tA = t0 + lane;
    const int tB = t0 + 32 + lane;
    const int spA = (tA + 1 < NS) ? spans[b * NS + tA + 1] : 0;
    const int spB = (tB + 1 < NS) ? spans[b * NS + tB + 1] : 0;
    const int nkA = nk_for(tA, mask_len, spA);
    const int nkB = nk_for(tB, mask_len, spB);

    // ---- warp-wide "row needed" bitmask over relative rows 0..67 ----
    // output t accumulates rows t+1..t+nk; lane covers [pos+1, pos+nk]
    unsigned long long mA = (((1ull << nkA) - 1ull) << (lane + 1));
    unsigned long long mBlo = 0ull;
    unsigned int       mBhi = 0u;
    {
        const unsigned long long bitsB = (1ull << nkB) - 1ull;   // nkB <= 4
        const int sB = 33 + lane;                                 // 33..64
        if (sB < 64) {
            mBlo = bitsB << sB;
            if (sB + nkB > 64) mBhi = (unsigned int)(bitsB >> (64 - sB));
        } else {
            mBhi = (unsigned int)bitsB;                           // sB == 64
        }
    }
    unsigned long long mloc = mA | mBlo;
    unsigned int lo = __reduce_or_sync(0xffffffffu, (unsigned int)mloc);
    unsigned int hi = __reduce_or_sync(0xffffffffu, (unsigned int)(mloc >> 32));
    const unsigned int m2 = __reduce_or_sync(0xffffffffu, mBhi);
    const unsigned long long m1 = ((unsigned long long)hi << 32) | lo;

    // window = mean rows wbase+1 .. wbase+7
    float4 w1 = redrow(p1);
    float4 w2 = redrow(p2);
    float4 w3 = redrow(p3);
    float4 r4 = redrow(p4);
    float4 r5 = redrow(p5);
    float4 r6 = redrow(p6);
    float4 r7 = redrow(p7);

    if (asc) {
        int t = t0;
        #pragma unroll 1
        for (int g = 0; g < 15; g++, t += 4) {
            const int rr = t - t0 + 8;       // relative row of first prefetch
            Raw4 q0, q1, q2, q3;
            LDROW_IF(q0, rr + 0, t + 8);
            LDROW_IF(q1, rr + 1, t + 9);
            LDROW_IF(q2, rr + 2, t + 10);
            LDROW_IF(q3, rr + 3, t + 11);
            const int nksel = (g < 8) ? nkA : nkB;
            const int nk0 = __shfl_sync(0xffffffffu, nksel, 4 * (g & 7) + 0);
            const int nk1 = __shfl_sync(0xffffffffu, nksel, 4 * (g & 7) + 1);
            const int nk2 = __shfl_sync(0xffffffffu, nksel, 4 * (g & 7) + 2);
            const int nk3 = __shfl_sync(0xffffffffu, nksel, 4 * (g & 7) + 3);
            emit(obase + (size_t)(t + 0) * ND4, nk0, w1, w2, w3, r4);
            emit(obase + (size_t)(t + 1) * ND4, nk1, w2, w3, r4, r5);
            emit(obase + (size_t)(t + 2) * ND4, nk2, w3, r4, r5, r6);
            emit(obase + (size_t)(t + 3) * ND4, nk3, r4, r5, r6, r7);
            w1 = r5; w2 = r6; w3 = r7;
            r4 = redrow(q0); r5 = redrow(q1); r6 = redrow(q2); r7 = redrow(q3);
        }
        {   // peeled last group (g=15, t=t0+60): no prefetch
            const int nk0 = __shfl_sync(0xffffffffu, nkB, 28);
            const int nk1 = __shfl_sync(0xffffffffu, nkB, 29);
            const int nk2 = __shfl_sync(0xffffffffu, nkB, 30);
            const int nk3 = __shfl_sync(0xffffffffu, nkB, 31);
            emit(obase + (size_t)(t + 0) * ND4, nk0, w1, w2, w3, r4);
            emit(obase + (size_t)(t + 1) * ND4, nk1, w2, w3, r4, r5);
            emit(obase + (size_t)(t + 2) * ND4, nk2, w3, r4, r5, r6);
            emit(obase + (size_t)(t + 3) * ND4, nk3, r4, r5, r6, r7);
        }
    } else {
        int t = t0 + 60;
        #pragma unroll 1
        for (int g = 15; g > 0; g--, t -= 4) {
            const int rr = t - t0 - 3;       // relative row of first prefetch
            Raw4 q0, q1, q2, q3;
            LDROW_IF(q0, rr + 0, t - 3);
            LDROW_IF(q1, rr + 1, t - 2);
            LDROW_IF(q2, rr + 2, t - 1);
            LDROW_IF(q3, rr + 3, t);
            const int nksel = (g < 8) ? nkA : nkB;
            const int nk0 = __shfl_sync(0xffffffffu, nksel, 4 * (g & 7) + 0);
            const int nk1 = __shfl_sync(0xffffffffu, nksel, 4 * (g & 7) + 1);
            const int nk2 = __shfl_sync(0xffffffffu, nksel, 4 * (g & 7) + 2);
            const int nk3 = __shfl_sync(0xffffffffu, nksel, 4 * (g & 7) + 3);
            emit(obase + (size_t)(t + 0) * ND4, nk0, w1, w2, w3, r4);
            emit(obase + (size_t)(t + 1) * ND4, nk1, w2, w3, r4, r5);
            emit(obase + (size_t)(t + 2) * ND4, nk2, w3, r4, r5, r6);
            emit(obase + (size_t)(t + 3) * ND4, nk3, r4, r5, r6, r7);
            const float4 ow1 = w1, ow2 = w2, ow3 = w3;
            w1 = redrow(q0); w2 = redrow(q1); w3 = redrow(q2); r4 = redrow(q3);
            r5 = ow1; r6 = ow2; r7 = ow3;
        }
        {   // peeled lowest group (g=0, t=t0): no prefetch
            const int nk0 = __shfl_sync(0xffffffffu, nkA, 0);
            const int nk1 = __shfl_sync(0xffffffffu, nkA, 1);
            const int nk2 = __shfl_sync(0xffffffffu, nkA, 2);
            const int nk3 = __shfl_sync(0xffffffffu, nkA, 3);
            emit(obase + (size_t)(t0 + 0) * ND4, nk0, w1, w2, w3, r4);
            emit(obase + (size_t)(t0 + 1) * ND4, nk1, w2, w3, r4, r5);
            emit(obase + (size_t)(t0 + 2) * ND4, nk2, w3, r4, r5, r6);
            emit(obase + (size_t)(t0 + 3) * ND4, nk3, r4, r5, r6, r7);
        }
    }
}

extern "C" void kernel_launch(void* const* d_in, const int* in_sizes, int n_in,
                              void* d_out, int out_size)
{
    const float* hs    = (const float*)d_in[0];   // (4,32,512,768) fp32
    const int*   spans = (const int*)  d_in[1];   // (32,512) int32
    const int*   masks = (const int*)  d_in[2];   // (32,512) int32
    float*       out   = (float*)d_out;           // (32,512,768) fp32

    lmencoder_warp6<<<GRID, 384>>>(hs, spans, masks, out);
}

// round 17
// speedup vs baseline: 1.0015x; 1.0015x over previous
#include <cuda_runtime.h>
#include <cstddef>

// Problem constants
#define NL 4
#define NB 32
#define NS 512
#define ND 768
#define MAX_SPAN 4

#define ND4 (ND / 4)                         // 192 float4 per row
#define LSTRIDE4 ((size_t)NB * NS * ND / 4)  // layer stride in float4
#define NDC 6                                // 128-wide d slices
#define TCHUNK 64                            // t per warp-tile
#define GRID 128                             // 128 blocks x 12 warps = 1536 exact

struct Raw4 { float4 a, b, c, d; };

// ---- raw 4-layer loads for row s (address clamp only; rows >= NS are
//      never accumulated because nk <= NS-1-t) ----
__device__ __forceinline__ Raw4 ldrow(const float4* __restrict__ base, int s)
{
    const int sc = s < NS - 1 ? s : NS - 1;
    const float4* p = base + (size_t)sc * ND4;
    Raw4 q;
    q.a = p[0];
    q.b = p[LSTRIDE4];
    q.c = p[2 * LSTRIDE4];
    q.d = p[3 * LSTRIDE4];
    return q;
}

__device__ __forceinline__ float4 redrow(const Raw4& q)
{
    float4 r;
    r.x = ((q.a.x + q.b.x) + (q.c.x + q.d.x)) * 0.25f;
    r.y = ((q.a.y + q.b.y) + (q.c.y + q.d.y)) * 0.25f;
    r.z = ((q.a.z + q.b.z) + (q.c.z + q.d.z)) * 0.25f;
    r.w = ((q.a.w + q.b.w) + (q.c.w + q.d.w)) * 0.25f;
    return r;
}

// ---- pooled output for one t: sum of first nk of {A,B,C,D} ----
__device__ __forceinline__ void emit(float4* __restrict__ op, int nk,
                                     const float4& A, const float4& B,
                                     const float4& C, const float4& D)
{
    float4 acc = make_float4(0.f, 0.f, 0.f, 0.f);
    if (nk > 0) { acc.x += A.x; acc.y += A.y; acc.z += A.z; acc.w += A.w; }
    if (nk > 1) { acc.x += B.x; acc.y += B.y; acc.z += B.z; acc.w += B.w; }
    if (nk > 2) { acc.x += C.x; acc.y += C.y; acc.z += C.z; acc.w += C.w; }
    if (nk > 3) { acc.x += D.x; acc.y += D.y; acc.z += D.z; acc.w += D.w; }
    __stcs(op, acc);
}

__device__ __forceinline__ int nk_for(int t, int mask_len, int span)
{
    int nk = 0;
    if (t < mask_len - 2) {
        nk = span;
        const int lim = NS - 1 - t;
        if (nk > lim) nk = lim;
        if (nk > MAX_SPAN) nk = MAX_SPAN;
        if (nk < 0) nk = 0;
    }
    return nk;
}

// r = row - t0, valid 0..67 (m1 covers 0..63, m2 covers 64..67)
__device__ __forceinline__ bool needed(unsigned long long m1, unsigned int m2, int r)
{
    return r < 64 ? (bool)((m1 >> r) & 1ull) : (bool)((m2 >> (r - 64)) & 1u);
}

// load row only if some output accumulates it; otherwise leave q untouched
#define LDROW_IF(q, r, s)                                         \
    do { if (needed(m1, m2, (r))) (q) = ldrow(base, (s)); } while (0)

__global__ __launch_bounds__(384, 1)
void lmencoder_warp6(const float* __restrict__ hs,
                     const int*   __restrict__ spans,
                     const int*   __restrict__ masks,
                     float*       __restrict__ out)
{
    const int lane = threadIdx.x & 31;
    const int wid  = threadIdx.x >> 5;          // 0..11
    const int tile = blockIdx.x * 12 + wid;     // 128*12 = 1536 exact
    const int dc   = tile % NDC;                // 0..5
    const int pair = tile / NDC;                // b*8 + tc
    const int b    = pair >> 3;
    const int tc   = pair & 7;
    const int t0   = tc * TCHUNK;
    const bool asc = (tc & 1) == 0;             // alternate direction by parity
    const int wbase = asc ? t0 : t0 + 60;       // first group's t

    const float4* base = reinterpret_cast<const float4*>(hs)
                         + (size_t)b * NS * ND4 + dc * 32 + lane;
    float4* obase = reinterpret_cast<float4*>(out)
                    + (size_t)b * NS * ND4 + dc * 32 + lane;

    // ---- prologue: 28 window loads issued unconditionally (DRAM busy early) ----
    const Raw4 p1 = ldrow(base, wbase + 1);
    const Raw4 p2 = ldrow(base, wbase + 2);
    const Raw4 p3 = ldrow(base, wbase + 3);
    const Raw4 p4 = ldrow(base, wbase + 4);
    const Raw4 p5 = ldrow(base, wbase + 5);
    const Raw4 p6 = ldrow(base, wbase + 6);
    const Raw4 p7 = ldrow(base, wbase + 7);

    // ---- mask_len + per-lane nk, overlapped with prologue load latency ----
    const int4* mrow4 = reinterpret_cast<const int4*>(masks + b * NS);
    int msum = 0;
    #pragma unroll
    for (int k = 0; k < 4; k++) {
        const int4 m = mrow4[lane + 32 * k];
        msum += (m.x + m.y) + (m.z + m.w);
    }
    #pragma unroll
    for (int off = 16; off; off >>= 1)
        msum += __shfl_xor_sync(0xffffffffu, msum, off);
    const int mask_len = msum;

    const int tA = t0 + lane;
    const int tB = t0 + 32 + lane;
    const int spA = (tA + 1 < NS) ? spans[b * NS + tA + 1] : 0;
    const int spB = (tB + 1 < NS) ? spans[b * NS + tB + 1] : 0;
    const int nkA = nk_for(tA, mask_len, spA);
    const int nkB = nk_for(tB, mask_len, spB);

    // ---- warp-wide "row needed" bitmask over relative rows 0..67 ----
    // output t accumulates rows t+1..t+nk; lane covers [pos+1, pos+nk]
    unsigned long long mA = (((1ull << nkA) - 1ull) << (lane + 1));
    unsigned long long mBlo = 0ull;
    unsigned int       mBhi = 0u;
    {
        const unsigned long long bitsB = (1ull << nkB) - 1ull;   // nkB <= 4
        const int sB = 33 + lane;                                 // 33..64
        if (sB < 64) {
            mBlo = bitsB << sB;
            if (sB + nkB > 64) mBhi = (unsigned int)(bitsB >> (64 - sB));
        } else {
            mBhi = (unsigned int)bitsB;                           // sB == 64
        }
    }
    unsigned long long mloc = mA | mBlo;
    unsigned int lo = __reduce_or_sync(0xffffffffu, (unsigned int)mloc);
    unsigned int hi = __reduce_or_sync(0xffffffffu, (unsigned int)(mloc >> 32));
    const unsigned int m2 = __reduce_or_sync(0xffffffffu, mBhi);
    const unsigned long long m1 = ((unsigned long long)hi << 32) | lo;

    // window = mean rows wbase+1 .. wbase+7
    float4 w1 = redrow(p1);
    float4 w2 = redrow(p2);
    float4 w3 = redrow(p3);
    float4 r4 = redrow(p4);
    float4 r5 = redrow(p5);
    float4 r6 = redrow(p6);
    float4 r7 = redrow(p7);

    if (asc) {
        int t = t0;
        #pragma unroll 1
        for (int g = 0; g < 15; g++, t += 4) {
            const int rr = t - t0 + 8;       // relative row of first prefetch
            Raw4 q0, q1, q2, q3;
            LDROW_IF(q0, rr + 0, t + 8);
            LDROW_IF(q1, rr + 1, t + 9);
            LDROW_IF(q2, rr + 2, t + 10);
            LDROW_IF(q3, rr + 3, t + 11);
            const int nksel = (g < 8) ? nkA : nkB;
            const int nk0 = __shfl_sync(0xffffffffu, nksel, 4 * (g & 7) + 0);
            const int nk1 = __shfl_sync(0xffffffffu, nksel, 4 * (g & 7) + 1);
            const int nk2 = __shfl_sync(0xffffffffu, nksel, 4 * (g & 7) + 2);
            const int nk3 = __shfl_sync(0xffffffffu, nksel, 4 * (g & 7) + 3);
            emit(obase + (size_t)(t + 0) * ND4, nk0, w1, w2, w3, r4);
            emit(obase + (size_t)(t + 1) * ND4, nk1, w2, w3, r4, r5);
            emit(obase + (size_t)(t + 2) * ND4, nk2, w3, r4, r5, r6);
            emit(obase + (size_t)(t + 3) * ND4, nk3, r4, r5, r6, r7);
            w1 = r5; w2 = r6; w3 = r7;
            r4 = redrow(q0); r5 = redrow(q1); r6 = redrow(q2); r7 = redrow(q3);
        }
        {   // peeled last group (g=15, t=t0+60): no prefetch
            const int nk0 = __shfl_sync(0xffffffffu, nkB, 28);
            const int nk1 = __shfl_sync(0xffffffffu, nkB, 29);
            const int nk2 = __shfl_sync(0xffffffffu, nkB, 30);
            const int nk3 = __shfl_sync(0xffffffffu, nkB, 31);
            emit(obase + (size_t)(t + 0) * ND4, nk0, w1, w2, w3, r4);
            emit(obase + (size_t)(t + 1) * ND4, nk1, w2, w3, r4, r5);
            emit(obase + (size_t)(t + 2) * ND4, nk2, w3, r4, r5, r6);
            emit(obase + (size_t)(t + 3) * ND4, nk3, r4, r5, r6, r7);
        }
    } else {
        int t = t0 + 60;
        #pragma unroll 1
        for (int g = 15; g > 0; g--, t -= 4) {
            const int rr = t - t0 - 3;       // relative row of first prefetch
            Raw4 q0, q1, q2, q3;
            LDROW_IF(q0, rr + 0, t - 3);
            LDROW_IF(q1, rr + 1, t - 2);
            LDROW_IF(q2, rr + 2, t - 1);
            LDROW_IF(q3, rr + 3, t);
            const int nksel = (g < 8) ? nkA : nkB;
            const int nk0 = __shfl_sync(0xffffffffu, nksel, 4 * (g & 7) + 0);
            const int nk1 = __shfl_sync(0xffffffffu, nksel, 4 * (g & 7) + 1);
            const int nk2 = __shfl_sync(0xffffffffu, nksel, 4 * (g & 7) + 2);
            const int nk3 = __shfl_sync(0xffffffffu, nksel, 4 * (g & 7) + 3);
            emit(obase + (size_t)(t + 0) * ND4, nk0, w1, w2, w3, r4);
            emit(obase + (size_t)(t + 1) * ND4, nk1, w2, w3, r4, r5);
            emit(obase + (size_t)(t + 2) * ND4, nk2, w3, r4, r5, r6);
            emit(obase + (size_t)(t + 3) * ND4, nk3, r4, r5, r6, r7);
            const float4 ow1 = w1, ow2 = w2, ow3 = w3;
            w1 = redrow(q0); w2 = redrow(q1); w3 = redrow(q2); r4 = redrow(q3);
            r5 = ow1; r6 = ow2; r7 = ow3;
        }
        {   // peeled lowest group (g=0, t=t0): no prefetch
            const int nk0 = __shfl_sync(0xffffffffu, nkA, 0);
            const int nk1 = __shfl_sync(0xffffffffu, nkA, 1);
            const int nk2 = __shfl_sync(0xffffffffu, nkA, 2);
            const int nk3 = __shfl_sync(0xffffffffu, nkA, 3);
            emit(obase + (size_t)(t0 + 0) * ND4, nk0, w1, w2, w3, r4);
            emit(obase + (size_t)(t0 + 1) * ND4, nk1, w2, w3, r4, r5);
            emit(obase + (size_t)(t0 + 2) * ND4, nk2, w3, r4, r5, r6);
            emit(obase + (size_t)(t0 + 3) * ND4, nk3, r4, r5, r6, r7);
        }
    }
}

extern "C" void kernel_launch(void* const* d_in, const int* in_sizes, int n_in,
                              void* d_out, int out_size)
{
    const float* hs    = (const float*)d_in[0];   // (4,32,512,768) fp32
    const int*   spans = (const int*)  d_in[1];   // (32,512) int32
    const int*   masks = (const int*)  d_in[2];   // (32,512) int32
    float*       out   = (float*)d_out;           // (32,512,768) fp32

    lmencoder_warp6<<<GRID, 384>>>(hs, spans, masks, out);
}